// round 7
// baseline (speedup 1.0000x reference)
#include <cuda_runtime.h>
#include <cuda_fp16.h>

typedef unsigned int u32;

#define NT  256
#define BM  128
#define BN  64
#define Dh  128
#define SEQ 2048
#define NIT (SEQ / BN)
#define LOG2E 1.44269504088896340736f

// ---- smem byte layout ----
#define QH_OFF 0
#define QL_OFF 32768
#define K_OFF  65536          // + buf*32768 ; lo at +16384
#define V_OFF  131072         // + buf*16384 (hi only)
#define SMEM_BYTES 163840

static __device__ __forceinline__ u32 cvta_smem(const void* p) {
    u32 a;
    asm("{ .reg .u64 t; cvta.to.shared.u64 t, %1; cvt.u32.u64 %0, t; }" : "=r"(a) : "l"(p));
    return a;
}
static __device__ __forceinline__ u32 swoff(int row, int ch) {
    return (u32)(row * 256 + ((ch ^ (row & 7)) << 4));
}
static __device__ __forceinline__ float ex2f(float x) {
    float y; asm("ex2.approx.f32 %0, %1;" : "=f"(y) : "f"(x)); return y;
}
static __device__ __forceinline__ u32 pack2(float x0, float x1) {
    __half2 h = __floats2half2_rn(x0, x1);
    return *(u32*)&h;
}
static __device__ __forceinline__ void split2(float x0, float x1, u32& hi, u32& lo) {
    __half2 h = __floats2half2_rn(x0, x1);
    float2  b = __half22float2(h);
    __half2 l = __floats2half2_rn(x0 - b.x, x1 - b.y);
    hi = *(u32*)&h; lo = *(u32*)&l;
}
static __device__ __forceinline__ void pf_l2(const void* p) {
    asm volatile("prefetch.global.L2 [%0];" :: "l"(p));
}

static __device__ __forceinline__ void ldm4(u32 addr, u32& r0, u32& r1, u32& r2, u32& r3) {
    asm volatile("ldmatrix.sync.aligned.m8n8.x4.shared.b16 {%0,%1,%2,%3}, [%4];"
                 : "=r"(r0), "=r"(r1), "=r"(r2), "=r"(r3) : "r"(addr));
}
static __device__ __forceinline__ void ldm4t(u32 addr, u32& r0, u32& r1, u32& r2, u32& r3) {
    asm volatile("ldmatrix.sync.aligned.m8n8.x4.trans.shared.b16 {%0,%1,%2,%3}, [%4];"
                 : "=r"(r0), "=r"(r1), "=r"(r2), "=r"(r3) : "r"(addr));
}
static __device__ __forceinline__ void mma(float* d, u32 a0, u32 a1, u32 a2, u32 a3, u32 b0, u32 b1) {
    asm volatile("mma.sync.aligned.m16n8k16.row.col.f32.f16.f16.f32 "
                 "{%0,%1,%2,%3}, {%4,%5,%6,%7}, {%8,%9}, {%0,%1,%2,%3};"
                 : "+f"(d[0]), "+f"(d[1]), "+f"(d[2]), "+f"(d[3])
                 : "r"(a0), "r"(a1), "r"(a2), "r"(a3), "r"(b0), "r"(b1));
}

static __device__ __forceinline__ void conv_k(const float* __restrict__ src,
                                              char* dh, char* dl, int tid) {
    #pragma unroll
    for (int p = 0; p < 4; p++) {
        int idx = tid + p * 256;
        int row = idx >> 4, ch = idx & 15;
        const float* s = src + (size_t)row * Dh + ch * 8;
        float4 a = *(const float4*)s;
        float4 b = *(const float4*)(s + 4);
        u32 h0, l0, h1, l1, h2, l2, h3, l3;
        split2(a.x, a.y, h0, l0); split2(a.z, a.w, h1, l1);
        split2(b.x, b.y, h2, l2); split2(b.z, b.w, h3, l3);
        u32 off = swoff(row, ch);
        *(uint4*)(dh + off) = make_uint4(h0, h1, h2, h3);
        *(uint4*)(dl + off) = make_uint4(l0, l1, l2, l3);
    }
}
static __device__ __forceinline__ void conv_v(const float* __restrict__ src,
                                              char* dh, int tid) {
    #pragma unroll
    for (int p = 0; p < 4; p++) {
        int idx = tid + p * 256;
        int row = idx >> 4, ch = idx & 15;
        const float* s = src + (size_t)row * Dh + ch * 8;
        float4 a = *(const float4*)s;
        float4 b = *(const float4*)(s + 4);
        u32 off = swoff(row, ch);
        *(uint4*)(dh + off) = make_uint4(pack2(a.x, a.y), pack2(a.z, a.w),
                                         pack2(b.x, b.y), pack2(b.z, b.w));
    }
}

__global__ __launch_bounds__(NT, 1)
void attn_hmma(const float* __restrict__ qg, const float* __restrict__ kg,
               const float* __restrict__ vg, const float* __restrict__ scg,
               float* __restrict__ og)
{
    extern __shared__ char sm[];
    const u32 smb = cvta_smem(sm);
    const int tid = threadIdx.x, lane = tid & 31, wid = tid >> 5;

    const int tile = blockIdx.x;
    const int bh   = blockIdx.y;
    const size_t base = (size_t)bh * SEQ * Dh;
    const float* Qg = qg + base + (size_t)tile * BM * Dh;
    const float* Kg = kg + base;
    const float* Vg = vg + base;
    float*       Og = og + base + (size_t)tile * BM * Dh;
    const float scL = scg[bh] * LOG2E;

    // ---- prologue: Q (scale folded, split) + tile 0 ----
    #pragma unroll
    for (int p = 0; p < 8; p++) {
        int idx = tid + p * 256;
        int row = idx >> 4, ch = idx & 15;
        const float* s = Qg + (size_t)row * Dh + ch * 8;
        float4 a = *(const float4*)s;
        float4 b = *(const float4*)(s + 4);
        u32 h0, l0, h1, l1, h2, l2, h3, l3;
        split2(a.x * scL, a.y * scL, h0, l0); split2(a.z * scL, a.w * scL, h1, l1);
        split2(b.x * scL, b.y * scL, h2, l2); split2(b.z * scL, b.w * scL, h3, l3);
        u32 off = swoff(row, ch);
        *(uint4*)(sm + QH_OFF + off) = make_uint4(h0, h1, h2, h3);
        *(uint4*)(sm + QL_OFF + off) = make_uint4(l0, l1, l2, l3);
    }
    conv_k(Kg, sm + K_OFF, sm + K_OFF + 16384, tid);
    conv_v(Vg, sm + V_OFF, tid);
    __syncthreads();

    // ---- per-warp state ----
    float oacc[16][4];
    #pragma unroll
    for (int f = 0; f < 16; f++)
        #pragma unroll
        for (int j = 0; j < 4; j++) oacc[f][j] = 0.f;
    float mA = -1e30f, mB = -1e30f, lA = 0.f, lB = 0.f;

    const int wr0 = wid * 16;
    const int qrow = wr0 + (lane & 15);
    const int qchh = lane >> 4;
    const int kn   = (lane & 7) + ((lane >> 4) << 3);
    const int kchh = (lane >> 3) & 1;
    const int vkey = (lane & 7) + (((lane >> 3) & 1) << 3);
    const int vchh = lane >> 4;

    // ---- hoist Q-hi fragments into registers (loop-invariant) ----
    u32 qh[8][4];
    #pragma unroll
    for (int kk = 0; kk < 8; kk++) {
        u32 qoff = swoff(qrow, kk * 2 + qchh);
        ldm4(smb + QH_OFF + qoff, qh[kk][0], qh[kk][1], qh[kk][2], qh[kk][3]);
    }

    #pragma unroll 1
    for (int n = 0; n < NIT; n++) {
        const int buf = n & 1;
        const u32 khb = smb + K_OFF + buf * 32768;
        const u32 klb = khb + 16384;
        const u32 vhb = smb + V_OFF + buf * 16384;

        // ---- prefetch next tile's f32 lines into L2 ----
        if (n + 1 < NIT) {
            const float* nk = Kg + (size_t)(n + 1) * BN * Dh;
            const float* nv = Vg + (size_t)(n + 1) * BN * Dh;
            pf_l2(nk + tid * 32);
            pf_l2(nv + tid * 32);
        }

        // ---- S = (Qh+Ql)(Kh+Kl)^T, 3 products ----
        float sacc[8][4];
        #pragma unroll
        for (int f = 0; f < 8; f++)
            #pragma unroll
            for (int j = 0; j < 4; j++) sacc[f][j] = 0.f;

        #pragma unroll
        for (int kk = 0; kk < 8; kk++) {
            u32 qoff = swoff(qrow, kk * 2 + qchh);
            u32 ql0, ql1, ql2, ql3;
            ldm4(smb + QL_OFF + qoff, ql0, ql1, ql2, ql3);
            #pragma unroll
            for (int jp = 0; jp < 4; jp++) {
                u32 koff = swoff(jp * 16 + kn, kk * 2 + kchh);
                u32 kb0, kb1, kb2, kb3, lb0, lb1, lb2, lb3;
                ldm4(khb + koff, kb0, kb1, kb2, kb3);
                ldm4(klb + koff, lb0, lb1, lb2, lb3);
                mma(sacc[jp * 2],     qh[kk][0], qh[kk][1], qh[kk][2], qh[kk][3], kb0, kb1);
                mma(sacc[jp * 2],     qh[kk][0], qh[kk][1], qh[kk][2], qh[kk][3], lb0, lb1);
                mma(sacc[jp * 2],     ql0, ql1, ql2, ql3, kb0, kb1);
                mma(sacc[jp * 2 + 1], qh[kk][0], qh[kk][1], qh[kk][2], qh[kk][3], kb2, kb3);
                mma(sacc[jp * 2 + 1], qh[kk][0], qh[kk][1], qh[kk][2], qh[kk][3], lb2, lb3);
                mma(sacc[jp * 2 + 1], ql0, ql1, ql2, ql3, kb2, kb3);
            }
        }

        // ---- online softmax (log2 domain) ----
        float rmaxA = -1e30f, rmaxB = -1e30f;
        #pragma unroll
        for (int f = 0; f < 8; f++) {
            rmaxA = fmaxf(rmaxA, fmaxf(sacc[f][0], sacc[f][1]));
            rmaxB = fmaxf(rmaxB, fmaxf(sacc[f][2], sacc[f][3]));
        }
        rmaxA = fmaxf(rmaxA, __shfl_xor_sync(0xffffffffu, rmaxA, 1));
        rmaxA = fmaxf(rmaxA, __shfl_xor_sync(0xffffffffu, rmaxA, 2));
        rmaxB = fmaxf(rmaxB, __shfl_xor_sync(0xffffffffu, rmaxB, 1));
        rmaxB = fmaxf(rmaxB, __shfl_xor_sync(0xffffffffu, rmaxB, 2));

        float mnA = fmaxf(mA, rmaxA), mnB = fmaxf(mB, rmaxB);
        float aA = ex2f(mA - mnA), aB = ex2f(mB - mnB);
        mA = mnA; mB = mnB;

        u32 ph[4][4];
        float sA = 0.f, sB = 0.f;
        #pragma unroll
        for (int kk = 0; kk < 4; kk++) {
            float p0 = ex2f(sacc[2 * kk][0] - mnA);
            float p1 = ex2f(sacc[2 * kk][1] - mnA);
            float p2 = ex2f(sacc[2 * kk][2] - mnB);
            float p3 = ex2f(sacc[2 * kk][3] - mnB);
            float p4 = ex2f(sacc[2 * kk + 1][0] - mnA);
            float p5 = ex2f(sacc[2 * kk + 1][1] - mnA);
            float p6 = ex2f(sacc[2 * kk + 1][2] - mnB);
            float p7 = ex2f(sacc[2 * kk + 1][3] - mnB);
            sA += (p0 + p1) + (p4 + p5);
            sB += (p2 + p3) + (p6 + p7);
            ph[kk][0] = pack2(p0, p1);
            ph[kk][1] = pack2(p2, p3);
            ph[kk][2] = pack2(p4, p5);
            ph[kk][3] = pack2(p6, p7);
        }
        sA += __shfl_xor_sync(0xffffffffu, sA, 1);
        sA += __shfl_xor_sync(0xffffffffu, sA, 2);
        sB += __shfl_xor_sync(0xffffffffu, sB, 1);
        sB += __shfl_xor_sync(0xffffffffu, sB, 2);
        lA = lA * aA + sA;
        lB = lB * aB + sB;

        // skip O-rescale when no lane's max moved (common after early tiles)
        if (__any_sync(0xffffffffu, (aA < 1.f) | (aB < 1.f))) {
            #pragma unroll
            for (int f = 0; f < 16; f++) {
                oacc[f][0] *= aA; oacc[f][1] *= aA;
                oacc[f][2] *= aB; oacc[f][3] *= aB;
            }
        }

        // ---- O += Ph @ Vh ----
        #pragma unroll
        for (int kk = 0; kk < 4; kk++) {
            #pragma unroll
            for (int dp = 0; dp < 8; dp++) {
                u32 voff = swoff(kk * 16 + vkey, dp * 2 + vchh);
                u32 vb0, vb1, vb2, vb3;
                ldm4t(vhb + voff, vb0, vb1, vb2, vb3);
                mma(oacc[2 * dp],     ph[kk][0], ph[kk][1], ph[kk][2], ph[kk][3], vb0, vb1);
                mma(oacc[2 * dp + 1], ph[kk][0], ph[kk][1], ph[kk][2], ph[kk][3], vb2, vb3);
            }
        }

        // ---- convert next tile (1 sync/iter) ----
        if (n + 1 < NIT) {
            conv_k(Kg + (size_t)(n + 1) * BN * Dh,
                   sm + K_OFF + (buf ^ 1) * 32768,
                   sm + K_OFF + (buf ^ 1) * 32768 + 16384, tid);
            conv_v(Vg + (size_t)(n + 1) * BN * Dh,
                   sm + V_OFF + (buf ^ 1) * 16384, tid);
        }
        __syncthreads();
    }

    // ---- epilogue ----
    const float iA = 1.f / lA, iB = 1.f / lB;
    const int ra = wr0 + (lane >> 2);
    const int rb = ra + 8;
    const int cb = 2 * (lane & 3);
    #pragma unroll
    for (int f = 0; f < 16; f++) {
        float2 va; va.x = oacc[f][0] * iA; va.y = oacc[f][1] * iA;
        float2 vb; vb.x = oacc[f][2] * iB; vb.y = oacc[f][3] * iB;
        *(float2*)(Og + (size_t)ra * Dh + f * 8 + cb) = va;
        *(float2*)(Og + (size_t)rb * Dh + f * 8 + cb) = vb;
    }
}

extern "C" void kernel_launch(void* const* d_in, const int* in_sizes, int n_in,
                              void* d_out, int out_size)
{
    const float* q     = (const float*)d_in[0];
    const float* k     = (const float*)d_in[1];
    const float* v     = (const float*)d_in[2];
    const float* scale = (const float*)d_in[3];
    float* out = (float*)d_out;

    cudaFuncSetAttribute(attn_hmma, cudaFuncAttributeMaxDynamicSharedMemorySize, SMEM_BYTES);
    dim3 grid(SEQ / BM, 4 * 16);
    attn_hmma<<<grid, NT, SMEM_BYTES>>>(q, k, v, scale, out);
}